// round 1
// baseline (speedup 1.0000x reference)
#include <cuda_runtime.h>

#define T_LEN  2048
#define NBATCH 2
#define DMODEL 512
#define SWIN   32
#define MROWS  4096      // T_LEN * NBATCH
#define BDIM   1024      // NBATCH * DMODEL

// ---------------- device scratch (allocation-free rule: __device__ globals) ----
__device__ float g_q  [MROWS * DMODEL];
__device__ float g_k  [MROWS * DMODEL];
__device__ float g_v  [MROWS * DMODEL];
__device__ float g_ek [MROWS * DMODEL];
__device__ float g_ekv[MROWS * DMODEL];
__device__ float g_csn[MROWS * DMODEL];
__device__ float g_csd[MROWS * DMODEL];
__device__ float g_y  [MROWS * DMODEL];
__device__ float g_colmax_part[32 * T_LEN];
__device__ float g_pbmax[T_LEN];           // relu(column-max of pos_bias)
__device__ float g_ml_part[16 * DMODEL];
__device__ float g_ml[DMODEL];
__device__ float g_expw[T_LEN * SWIN];

// ---------------- packed f32x2 helpers (FFMA2 — see SASS_QUICKREF) ------------
__device__ __forceinline__ unsigned long long pack2(float lo, float hi) {
    unsigned long long r;
    asm("mov.b64 %0, {%1, %2};" : "=l"(r) : "f"(lo), "f"(hi));
    return r;
}
__device__ __forceinline__ void unpack2(unsigned long long v, float& lo, float& hi) {
    asm("mov.b64 {%0, %1}, %2;" : "=f"(lo), "=f"(hi) : "l"(v));
}
__device__ __forceinline__ unsigned long long ffma2(unsigned long long a,
                                                    unsigned long long b,
                                                    unsigned long long c) {
    unsigned long long d;
    asm("fma.rn.f32x2 %0, %1, %2, %3;" : "=l"(d) : "l"(a), "l"(b), "l"(c));
    return d;
}

// ---------------- column max of pos_bias, 2-phase --------------------------
__global__ void colmax_part_kernel(const float* __restrict__ pb) {
    int c  = blockIdx.x * 256 + threadIdx.x;     // column 0..2047
    int r0 = blockIdx.y * 64;                    // row chunk
    float m = -3.402823e38f;
#pragma unroll 4
    for (int r = 0; r < 64; ++r)
        m = fmaxf(m, pb[(size_t)(r0 + r) * T_LEN + c]);
    g_colmax_part[blockIdx.y * T_LEN + c] = m;
}

__global__ void colmax_comb_kernel() {
    int c = blockIdx.x * 256 + threadIdx.x;
    float m = -3.402823e38f;
#pragma unroll
    for (int i = 0; i < 32; ++i)
        m = fmaxf(m, g_colmax_part[i * T_LEN + c]);
    g_pbmax[c] = fmaxf(m, 0.0f);                 // relu folded in
}

// ---------------- fp32 GEMM body: out[4096,512] = X[4096,512] @ W[512,512]^T + bias
// 128x128 tile, BK=16, 256 threads, 8x8 per thread, FFMA2 inner loop.
__device__ __forceinline__ void gemm_body(const float* __restrict__ X,
                                          const float* __restrict__ W,
                                          const float* __restrict__ bias,
                                          float* __restrict__ out) {
    __shared__ float As[16][128];
    __shared__ float Bs[16][128];

    const int tid = threadIdx.x;
    const int m0  = blockIdx.y * 128;
    const int n0  = blockIdx.x * 128;
    const int tx  = tid & 15;        // 0..15 -> n micro-tile
    const int ty  = tid >> 4;        // 0..15 -> m micro-tile
    const int lrow = tid >> 2;       // 0..63
    const int lkq  = (tid & 3) * 4;  // 0,4,8,12

    const float* xA  = X + (size_t)(m0 + lrow) * 512 + lkq;
    const float* xA2 = xA + (size_t)64 * 512;
    const float* wB  = W + (size_t)(n0 + lrow) * 512 + lkq;
    const float* wB2 = wB + (size_t)64 * 512;

    unsigned long long acc[8][4];
#pragma unroll
    for (int i = 0; i < 8; ++i)
#pragma unroll
        for (int j = 0; j < 4; ++j) acc[i][j] = 0ULL;

    for (int k0 = 0; k0 < 512; k0 += 16) {
        float4 a0 = *(const float4*)(xA  + k0);
        float4 a1 = *(const float4*)(xA2 + k0);
        float4 b0 = *(const float4*)(wB  + k0);
        float4 b1 = *(const float4*)(wB2 + k0);
        __syncthreads();
        As[lkq + 0][lrow]      = a0.x; As[lkq + 1][lrow]      = a0.y;
        As[lkq + 2][lrow]      = a0.z; As[lkq + 3][lrow]      = a0.w;
        As[lkq + 0][lrow + 64] = a1.x; As[lkq + 1][lrow + 64] = a1.y;
        As[lkq + 2][lrow + 64] = a1.z; As[lkq + 3][lrow + 64] = a1.w;
        Bs[lkq + 0][lrow]      = b0.x; Bs[lkq + 1][lrow]      = b0.y;
        Bs[lkq + 2][lrow]      = b0.z; Bs[lkq + 3][lrow]      = b0.w;
        Bs[lkq + 0][lrow + 64] = b1.x; Bs[lkq + 1][lrow + 64] = b1.y;
        Bs[lkq + 2][lrow + 64] = b1.z; Bs[lkq + 3][lrow + 64] = b1.w;
        __syncthreads();

#pragma unroll
        for (int kk = 0; kk < 16; ++kk) {
            float4 alo = *(const float4*)&As[kk][ty * 8];
            float4 ahi = *(const float4*)&As[kk][ty * 8 + 4];
            ulonglong2 bq0 = *(const ulonglong2*)&Bs[kk][tx * 8];
            ulonglong2 bq1 = *(const ulonglong2*)&Bs[kk][tx * 8 + 4];
            float a[8] = {alo.x, alo.y, alo.z, alo.w, ahi.x, ahi.y, ahi.z, ahi.w};
#pragma unroll
            for (int i = 0; i < 8; ++i) {
                unsigned long long aa = pack2(a[i], a[i]);
                acc[i][0] = ffma2(aa, bq0.x, acc[i][0]);
                acc[i][1] = ffma2(aa, bq0.y, acc[i][1]);
                acc[i][2] = ffma2(aa, bq1.x, acc[i][2]);
                acc[i][3] = ffma2(aa, bq1.y, acc[i][3]);
            }
        }
    }

    float bvals[8];
#pragma unroll
    for (int j = 0; j < 8; ++j) bvals[j] = bias[n0 + tx * 8 + j];

#pragma unroll
    for (int i = 0; i < 8; ++i) {
        float o[8];
#pragma unroll
        for (int j = 0; j < 4; ++j) unpack2(acc[i][j], o[2 * j], o[2 * j + 1]);
        float4 v0 = {o[0] + bvals[0], o[1] + bvals[1], o[2] + bvals[2], o[3] + bvals[3]};
        float4 v1 = {o[4] + bvals[4], o[5] + bvals[5], o[6] + bvals[6], o[7] + bvals[7]};
        float* op = out + (size_t)(m0 + ty * 8 + i) * 512 + n0 + tx * 8;
        *(float4*)(op)     = v0;
        *(float4*)(op + 4) = v1;
    }
}

__global__ void __launch_bounds__(256) gemm_qkv_kernel(
    const float* __restrict__ xq, const float* __restrict__ xk, const float* __restrict__ xv,
    const float* __restrict__ Wq, const float* __restrict__ bq,
    const float* __restrict__ Wk, const float* __restrict__ bk,
    const float* __restrict__ Wv, const float* __restrict__ bv) {
    if (blockIdx.z == 0)      gemm_body(xq, Wq, bq, g_q);
    else if (blockIdx.z == 1) gemm_body(xk, Wk, bk, g_k);
    else                      gemm_body(xv, Wv, bv, g_v);
}

__global__ void __launch_bounds__(256) gemm_o_kernel(
    const float* __restrict__ Wo, const float* __restrict__ bo, float* __restrict__ out) {
    gemm_body(g_y, Wo, bo, out);
}

// ---------------- max_logit[d] = max_t ( k[t,0,d] + relu(pbmax[t]) ), 2-phase --
__global__ void ml_part_kernel() {
    int d  = blockIdx.x * 256 + threadIdx.x;     // 0..511
    int t0 = blockIdx.y * 128;
    float m = -3.402823e38f;
#pragma unroll 4
    for (int tt = 0; tt < 128; ++tt) {
        int t = t0 + tt;
        m = fmaxf(m, g_k[(size_t)t * BDIM + d] + g_pbmax[t]);
    }
    g_ml_part[blockIdx.y * DMODEL + d] = m;
}

__global__ void ml_comb_kernel() {
    int d = blockIdx.x * 256 + threadIdx.x;
    float m = -3.402823e38f;
#pragma unroll
    for (int i = 0; i < 16; ++i) m = fmaxf(m, g_ml_part[i * DMODEL + d]);
    g_ml[d] = m;
}

// ---------------- ek/ekv + inclusive cumsum over t (serial per (b,d) column) --
__global__ void cumsum_kernel() {
    int bd = blockIdx.x * 256 + threadIdx.x;     // 0..1023
    int d  = bd & (DMODEL - 1);
    float ml = g_ml[d];
    float sn = 0.0f, sd = 0.0f;
#pragma unroll 4
    for (int t = 0; t < T_LEN; ++t) {
        size_t off = (size_t)t * BDIM + bd;
        float e  = __expf(g_k[off] - ml);
        float ev = e * g_v[off];
        sn += ev;
        sd += e;
        g_ek[off]  = e;
        g_ekv[off] = ev;
        g_csn[off] = sn;
        g_csd[off] = sd;
    }
}

// ---------------- expw[t,j] = exp(pb[t, t-S+1+j]) (0 if out of range) ---------
__global__ void expw_kernel(const float* __restrict__ pb) {
    int i = blockIdx.x * 256 + threadIdx.x;      // 0..65535
    int t = i >> 5;
    int j = i & 31;
    int idx = t - SWIN + 1 + j;
    g_expw[i] = (idx >= 0) ? __expf(pb[(size_t)t * T_LEN + idx]) : 0.0f;
}

// ---------------- window + prefix combine: y = sigmoid(q)*(num/den) ----------
// Each thread: one (b,d), 4 consecutive t. Band rows loaded once, reused 4x.
__global__ void __launch_bounds__(256) aft_out_kernel() {
    int bd = blockIdx.x * 256 + threadIdx.x;     // 0..1023
    int t0 = blockIdx.y * 4;

    float num[4] = {0.f, 0.f, 0.f, 0.f};
    float den[4] = {0.f, 0.f, 0.f, 0.f};

    int lo = t0 - SWIN + 1;
    if (lo < 0) lo = 0;

    for (int idx = lo; idx <= t0 + 3; ++idx) {
        size_t off = (size_t)idx * BDIM + bd;
        float ek  = g_ek[off];
        float ekv = g_ekv[off];
#pragma unroll
        for (int r = 0; r < 4; ++r) {
            int t = t0 + r;
            if (idx <= t && idx >= t - (SWIN - 1)) {
                float w = __ldg(&g_expw[t * SWIN + (idx - t + SWIN - 1)]);
                num[r] += w * ekv;
                den[r] += w * ek;
            }
        }
    }

#pragma unroll
    for (int r = 0; r < 4; ++r) {
        int t = t0 + r;
        float n = num[r], dn = den[r];
        if (t >= SWIN) {
            size_t poff = (size_t)(t - SWIN) * BDIM + bd;
            n  += g_csn[poff];
            dn += g_csd[poff];
        }
        size_t off = (size_t)t * BDIM + bd;
        float q  = g_q[off];
        float sg = 1.0f / (1.0f + __expf(-q));
        g_y[off] = sg * n / dn;
    }
}

// ---------------- launch ------------------------------------------------------
extern "C" void kernel_launch(void* const* d_in, const int* in_sizes, int n_in,
                              void* d_out, int out_size) {
    const float* query = (const float*)d_in[0];
    const float* key   = (const float*)d_in[1];
    const float* value = (const float*)d_in[2];
    const float* Wq    = (const float*)d_in[3];
    const float* bq    = (const float*)d_in[4];
    const float* Wk    = (const float*)d_in[5];
    const float* bk    = (const float*)d_in[6];
    const float* Wv    = (const float*)d_in[7];
    const float* bv    = (const float*)d_in[8];
    const float* pb    = (const float*)d_in[9];
    const float* Wo    = (const float*)d_in[10];
    const float* bo    = (const float*)d_in[11];
    float* out = (float*)d_out;

    colmax_part_kernel<<<dim3(8, 32), 256>>>(pb);
    colmax_comb_kernel<<<8, 256>>>();

    gemm_qkv_kernel<<<dim3(4, 32, 3), 256>>>(query, key, value, Wq, bq, Wk, bk, Wv, bv);

    ml_part_kernel<<<dim3(2, 16), 256>>>();
    ml_comb_kernel<<<2, 256>>>();

    cumsum_kernel<<<4, 256>>>();

    expw_kernel<<<(T_LEN * SWIN) / 256, 256>>>(pb);

    aft_out_kernel<<<dim3(4, 512), 256>>>();

    gemm_o_kernel<<<dim3(4, 32), 256>>>(Wo, bo, out);
}

// round 2
// speedup vs baseline: 2.6909x; 2.6909x over previous
#include <cuda_runtime.h>

#define T_LEN  2048
#define NBATCH 2
#define DMODEL 512
#define SWIN   32
#define MROWS  4096      // T_LEN * NBATCH
#define BDIM   1024      // NBATCH * DMODEL
#define NCHUNK 64        // T_LEN / 32

// ---------------- device scratch (allocation-free rule: __device__ globals) ----
__device__ float g_q  [MROWS * DMODEL];
__device__ float g_k  [MROWS * DMODEL];
__device__ float g_v  [MROWS * DMODEL];
__device__ float g_ek [MROWS * DMODEL];
__device__ float g_ekv[MROWS * DMODEL];
__device__ float g_csn[MROWS * DMODEL];
__device__ float g_csd[MROWS * DMODEL];
__device__ float g_y  [MROWS * DMODEL];
__device__ float g_colmax_part[32 * T_LEN];
__device__ float g_pbmax[T_LEN];           // relu(column-max of pos_bias)
__device__ float g_ml_part[NCHUNK * DMODEL];
__device__ float g_ml[DMODEL];
__device__ float g_expw[T_LEN * SWIN];
__device__ float g_psn[NCHUNK * BDIM];     // scan chunk partials (num)
__device__ float g_psd[NCHUNK * BDIM];     // scan chunk partials (den)

// ---------------- packed f32x2 helpers (FFMA2 — see SASS_QUICKREF) ------------
__device__ __forceinline__ unsigned long long pack2(float lo, float hi) {
    unsigned long long r;
    asm("mov.b64 %0, {%1, %2};" : "=l"(r) : "f"(lo), "f"(hi));
    return r;
}
__device__ __forceinline__ void unpack2(unsigned long long v, float& lo, float& hi) {
    asm("mov.b64 {%0, %1}, %2;" : "=f"(lo), "=f"(hi) : "l"(v));
}
__device__ __forceinline__ unsigned long long ffma2(unsigned long long a,
                                                    unsigned long long b,
                                                    unsigned long long c) {
    unsigned long long d;
    asm("fma.rn.f32x2 %0, %1, %2, %3;" : "=l"(d) : "l"(a), "l"(b), "l"(c));
    return d;
}

// ---------------- column max of pos_bias, 2-phase --------------------------
__global__ void colmax_part_kernel(const float* __restrict__ pb) {
    int c  = blockIdx.x * 256 + threadIdx.x;     // column 0..2047
    int r0 = blockIdx.y * 64;                    // row chunk
    float m = -3.402823e38f;
#pragma unroll 4
    for (int r = 0; r < 64; ++r)
        m = fmaxf(m, pb[(size_t)(r0 + r) * T_LEN + c]);
    g_colmax_part[blockIdx.y * T_LEN + c] = m;
}

__global__ void colmax_comb_kernel() {
    int c = blockIdx.x * 256 + threadIdx.x;
    float m = -3.402823e38f;
#pragma unroll
    for (int i = 0; i < 32; ++i)
        m = fmaxf(m, g_colmax_part[i * T_LEN + c]);
    g_pbmax[c] = fmaxf(m, 0.0f);                 // relu folded in
}

// ---------------- fp32 GEMM body: out[4096,512] = X[4096,512] @ W[512,512]^T + bias
// 128x128 tile, BK=16, 256 threads, 8x8 per thread, FFMA2 inner loop.
__device__ __forceinline__ void gemm_body(const float* __restrict__ X,
                                          const float* __restrict__ W,
                                          const float* __restrict__ bias,
                                          float* __restrict__ out) {
    __shared__ float As[16][128];
    __shared__ float Bs[16][128];

    const int tid = threadIdx.x;
    const int m0  = blockIdx.y * 128;
    const int n0  = blockIdx.x * 128;
    const int tx  = tid & 15;        // 0..15 -> n micro-tile
    const int ty  = tid >> 4;        // 0..15 -> m micro-tile
    const int lrow = tid >> 2;       // 0..63
    const int lkq  = (tid & 3) * 4;  // 0,4,8,12

    const float* xA  = X + (size_t)(m0 + lrow) * 512 + lkq;
    const float* xA2 = xA + (size_t)64 * 512;
    const float* wB  = W + (size_t)(n0 + lrow) * 512 + lkq;
    const float* wB2 = wB + (size_t)64 * 512;

    unsigned long long acc[8][4];
#pragma unroll
    for (int i = 0; i < 8; ++i)
#pragma unroll
        for (int j = 0; j < 4; ++j) acc[i][j] = 0ULL;

    for (int k0 = 0; k0 < 512; k0 += 16) {
        float4 a0 = *(const float4*)(xA  + k0);
        float4 a1 = *(const float4*)(xA2 + k0);
        float4 b0 = *(const float4*)(wB  + k0);
        float4 b1 = *(const float4*)(wB2 + k0);
        __syncthreads();
        As[lkq + 0][lrow]      = a0.x; As[lkq + 1][lrow]      = a0.y;
        As[lkq + 2][lrow]      = a0.z; As[lkq + 3][lrow]      = a0.w;
        As[lkq + 0][lrow + 64] = a1.x; As[lkq + 1][lrow + 64] = a1.y;
        As[lkq + 2][lrow + 64] = a1.z; As[lkq + 3][lrow + 64] = a1.w;
        Bs[lkq + 0][lrow]      = b0.x; Bs[lkq + 1][lrow]      = b0.y;
        Bs[lkq + 2][lrow]      = b0.z; Bs[lkq + 3][lrow]      = b0.w;
        Bs[lkq + 0][lrow + 64] = b1.x; Bs[lkq + 1][lrow + 64] = b1.y;
        Bs[lkq + 2][lrow + 64] = b1.z; Bs[lkq + 3][lrow + 64] = b1.w;
        __syncthreads();

#pragma unroll
        for (int kk = 0; kk < 16; ++kk) {
            float4 alo = *(const float4*)&As[kk][ty * 8];
            float4 ahi = *(const float4*)&As[kk][ty * 8 + 4];
            ulonglong2 bq0 = *(const ulonglong2*)&Bs[kk][tx * 8];
            ulonglong2 bq1 = *(const ulonglong2*)&Bs[kk][tx * 8 + 4];
            float a[8] = {alo.x, alo.y, alo.z, alo.w, ahi.x, ahi.y, ahi.z, ahi.w};
#pragma unroll
            for (int i = 0; i < 8; ++i) {
                unsigned long long aa = pack2(a[i], a[i]);
                acc[i][0] = ffma2(aa, bq0.x, acc[i][0]);
                acc[i][1] = ffma2(aa, bq0.y, acc[i][1]);
                acc[i][2] = ffma2(aa, bq1.x, acc[i][2]);
                acc[i][3] = ffma2(aa, bq1.y, acc[i][3]);
            }
        }
    }

    float bvals[8];
#pragma unroll
    for (int j = 0; j < 8; ++j) bvals[j] = bias[n0 + tx * 8 + j];

#pragma unroll
    for (int i = 0; i < 8; ++i) {
        float o[8];
#pragma unroll
        for (int j = 0; j < 4; ++j) unpack2(acc[i][j], o[2 * j], o[2 * j + 1]);
        float4 v0 = {o[0] + bvals[0], o[1] + bvals[1], o[2] + bvals[2], o[3] + bvals[3]};
        float4 v1 = {o[4] + bvals[4], o[5] + bvals[5], o[6] + bvals[6], o[7] + bvals[7]};
        float* op = out + (size_t)(m0 + ty * 8 + i) * 512 + n0 + tx * 8;
        *(float4*)(op)     = v0;
        *(float4*)(op + 4) = v1;
    }
}

__global__ void __launch_bounds__(256) gemm_qkv_kernel(
    const float* __restrict__ xq, const float* __restrict__ xk, const float* __restrict__ xv,
    const float* __restrict__ Wq, const float* __restrict__ bq,
    const float* __restrict__ Wk, const float* __restrict__ bk,
    const float* __restrict__ Wv, const float* __restrict__ bv) {
    if (blockIdx.z == 0)      gemm_body(xq, Wq, bq, g_q);
    else if (blockIdx.z == 1) gemm_body(xk, Wk, bk, g_k);
    else                      gemm_body(xv, Wv, bv, g_v);
}

__global__ void __launch_bounds__(256) gemm_o_kernel(
    const float* __restrict__ Wo, const float* __restrict__ bo, float* __restrict__ out) {
    gemm_body(g_y, Wo, bo, out);
}

// ---------------- max_logit[d] = max_t ( k[t,0,d] + relu(pbmax[t]) ), 2-phase --
// grid (2, 64): 32-row chunks, full-chip occupancy, coalesced 512-wide reads.
__global__ void ml_part_kernel() {
    int d  = blockIdx.x * 256 + threadIdx.x;     // 0..511
    int t0 = blockIdx.y * 32;
    float m = -3.402823e38f;
#pragma unroll 8
    for (int tt = 0; tt < 32; ++tt) {
        int t = t0 + tt;
        m = fmaxf(m, g_k[(size_t)t * BDIM + d] + g_pbmax[t]);
    }
    g_ml_part[blockIdx.y * DMODEL + d] = m;
}

__global__ void ml_comb_kernel() {
    int d = blockIdx.x * 256 + threadIdx.x;
    float m = -3.402823e38f;
#pragma unroll
    for (int i = 0; i < NCHUNK; ++i) m = fmaxf(m, g_ml_part[i * DMODEL + d]);
    g_ml[d] = m;
}

// ---------------- 3-phase parallel scan over t (64 chunks x 32) ---------------
// Phase A: ek/ekv + per-chunk partial sums.   grid (4, 64)
__global__ void scan_partial_kernel() {
    int bd = blockIdx.x * 256 + threadIdx.x;     // 0..1023
    int c  = blockIdx.y;                         // chunk 0..63
    int d  = bd & (DMODEL - 1);
    float ml = g_ml[d];
    float sn = 0.0f, sd = 0.0f;
    size_t base = (size_t)c * 32 * BDIM + bd;
#pragma unroll 8
    for (int i = 0; i < 32; ++i) {
        size_t off = base + (size_t)i * BDIM;
        float e  = __expf(g_k[off] - ml);
        float ev = e * g_v[off];
        g_ek[off]  = e;
        g_ekv[off] = ev;
        sn += ev;
        sd += e;
    }
    g_psn[c * BDIM + bd] = sn;
    g_psd[c * BDIM + bd] = sd;
}

// Phase B: exclusive prefix over the 64 chunk partials.  1 block, 1024 threads.
__global__ void __launch_bounds__(1024) scan_prefix_kernel() {
    int bd = threadIdx.x;
    float sn = 0.0f, sd = 0.0f;
#pragma unroll 4
    for (int c = 0; c < NCHUNK; ++c) {
        float tn = g_psn[c * BDIM + bd];
        float td = g_psd[c * BDIM + bd];
        g_psn[c * BDIM + bd] = sn;   // exclusive prefix
        g_psd[c * BDIM + bd] = sd;
        sn += tn;
        sd += td;
    }
}

// Phase C: inclusive cumsum within chunk + chunk offset.  grid (4, 64)
__global__ void scan_final_kernel() {
    int bd = blockIdx.x * 256 + threadIdx.x;
    int c  = blockIdx.y;
    float sn = g_psn[c * BDIM + bd];
    float sd = g_psd[c * BDIM + bd];
    size_t base = (size_t)c * 32 * BDIM + bd;
#pragma unroll 8
    for (int i = 0; i < 32; ++i) {
        size_t off = base + (size_t)i * BDIM;
        sn += g_ekv[off];
        sd += g_ek[off];
        g_csn[off] = sn;
        g_csd[off] = sd;
    }
}

// ---------------- expw[t,j] = exp(pb[t, t-S+1+j]) (0 if out of range) ---------
__global__ void expw_kernel(const float* __restrict__ pb) {
    int i = blockIdx.x * 256 + threadIdx.x;      // 0..65535
    int t = i >> 5;
    int j = i & 31;
    int idx = t - SWIN + 1 + j;
    g_expw[i] = (idx >= 0) ? __expf(pb[(size_t)t * T_LEN + idx]) : 0.0f;
}

// ---------------- window + prefix combine: y = sigmoid(q)*(num/den) ----------
// Each thread: one (b,d), 4 consecutive t. Band rows loaded once, reused 4x.
// Window weights for the block's 4 t values staged in shared memory.
__global__ void __launch_bounds__(256) aft_out_kernel() {
    __shared__ float wgt[4 * SWIN];
    int bd = blockIdx.x * 256 + threadIdx.x;     // 0..1023
    int t0 = blockIdx.y * 4;

    if (threadIdx.x < 4 * SWIN) {
        int r = threadIdx.x >> 5;
        int j = threadIdx.x & 31;
        wgt[threadIdx.x] = g_expw[(t0 + r) * SWIN + j];
    }
    __syncthreads();

    float num[4] = {0.f, 0.f, 0.f, 0.f};
    float den[4] = {0.f, 0.f, 0.f, 0.f};

    int lo = t0 - SWIN + 1;
    if (lo < 0) lo = 0;

    for (int idx = lo; idx <= t0 + 3; ++idx) {
        size_t off = (size_t)idx * BDIM + bd;
        float ek  = g_ek[off];
        float ekv = g_ekv[off];
#pragma unroll
        for (int r = 0; r < 4; ++r) {
            int t = t0 + r;
            int j = idx - t + SWIN - 1;          // window position
            if (j >= 0 && j < SWIN) {
                float w = wgt[r * SWIN + j];
                num[r] += w * ekv;
                den[r] += w * ek;
            }
        }
    }

#pragma unroll
    for (int r = 0; r < 4; ++r) {
        int t = t0 + r;
        float n = num[r], dn = den[r];
        if (t >= SWIN) {
            size_t poff = (size_t)(t - SWIN) * BDIM + bd;
            n  += g_csn[poff];
            dn += g_csd[poff];
        }
        size_t off = (size_t)t * BDIM + bd;
        float q  = g_q[off];
        float sg = 1.0f / (1.0f + __expf(-q));
        g_y[off] = sg * n / dn;
    }
}

// ---------------- launch ------------------------------------------------------
extern "C" void kernel_launch(void* const* d_in, const int* in_sizes, int n_in,
                              void* d_out, int out_size) {
    const float* query = (const float*)d_in[0];
    const float* key   = (const float*)d_in[1];
    const float* value = (const float*)d_in[2];
    const float* Wq    = (const float*)d_in[3];
    const float* bq    = (const float*)d_in[4];
    const float* Wk    = (const float*)d_in[5];
    const float* bk    = (const float*)d_in[6];
    const float* Wv    = (const float*)d_in[7];
    const float* bv    = (const float*)d_in[8];
    const float* pb    = (const float*)d_in[9];
    const float* Wo    = (const float*)d_in[10];
    const float* bo    = (const float*)d_in[11];
    float* out = (float*)d_out;

    colmax_part_kernel<<<dim3(8, 32), 256>>>(pb);
    colmax_comb_kernel<<<8, 256>>>();

    gemm_qkv_kernel<<<dim3(4, 32, 3), 256>>>(query, key, value, Wq, bq, Wk, bk, Wv, bv);

    ml_part_kernel<<<dim3(2, 64), 256>>>();
    ml_comb_kernel<<<2, 256>>>();

    scan_partial_kernel<<<dim3(4, 64), 256>>>();
    scan_prefix_kernel<<<1, 1024>>>();
    scan_final_kernel<<<dim3(4, 64), 256>>>();

    expw_kernel<<<(T_LEN * SWIN) / 256, 256>>>(pb);

    aft_out_kernel<<<dim3(4, 512), 256>>>();

    gemm_o_kernel<<<dim3(4, 32), 256>>>(Wo, bo, out);
}

// round 7
// speedup vs baseline: 4.8547x; 1.8041x over previous
#include <cuda_runtime.h>
#include <cuda_bf16.h>
#include <cstdint>

#define T_LEN  2048
#define NBATCH 2
#define DMODEL 512
#define SWIN   32
#define MROWS  4096      // T_LEN * NBATCH
#define BDIM   1024      // NBATCH * DMODEL
#define NCHUNK 64        // T_LEN / 32

// ---------------- device scratch (allocation-free rule: __device__ globals) ----
__device__ float g_q  [MROWS * DMODEL];
__device__ float g_k  [MROWS * DMODEL];
__device__ float g_v  [MROWS * DMODEL];
__device__ float g_ek [MROWS * DMODEL];
__device__ float g_ekv[MROWS * DMODEL];
__device__ float g_csn[MROWS * DMODEL];
__device__ float g_csd[MROWS * DMODEL];
__device__ float g_y  [MROWS * DMODEL];
__device__ float g_colmax_part[32 * T_LEN];
__device__ float g_pbmax[T_LEN];
__device__ float g_ml_part[NCHUNK * DMODEL];
__device__ float g_ml[DMODEL];
__device__ float g_expw[T_LEN * SWIN];
__device__ float g_psn[NCHUNK * BDIM];
__device__ float g_psd[NCHUNK * BDIM];

// ================= bf16x3 split-precision warp-MMA GEMM ========================
// out[4096,512] = X[4096,512] @ W[512,512]^T + bias
// x = hi + lo (bf16 each); x*y ~= hi*hi + hi*lo + lo*hi (fp32 accum).
// CTA tile 128x128, BK=32, 8 warps of 64x32, double-buffered smem.

#define LDT     40                       // bf16 elems per smem row (32 + 8 pad)
#define TILE_BYTES (128 * LDT * 2)       // one bf16 tile: 10240 B
#define STAGE_BYTES (4 * TILE_BYTES)     // Ah, Al, Bh, Bl
#define SMEM_MMA (2 * STAGE_BYTES)       // 81920 B

__device__ __forceinline__ uint32_t pack_bf16(float a, float b) {
    __nv_bfloat162 t = __floats2bfloat162_rn(a, b);
    return *(uint32_t*)&t;
}

__device__ __forceinline__ void mma_bf16(float* c, const uint32_t* a, const uint32_t* b) {
    asm volatile(
        "mma.sync.aligned.m16n8k16.row.col.f32.bf16.bf16.f32 "
        "{%0,%1,%2,%3}, {%4,%5,%6,%7}, {%8,%9}, {%0,%1,%2,%3};"
        : "+f"(c[0]), "+f"(c[1]), "+f"(c[2]), "+f"(c[3])
        : "r"(a[0]), "r"(a[1]), "r"(a[2]), "r"(a[3]), "r"(b[0]), "r"(b[1]));
}

__device__ __forceinline__ void gemm_mma_body(const float* __restrict__ X,
                                              const float* __restrict__ W,
                                              const float* __restrict__ bias,
                                              float* __restrict__ out) {
    extern __shared__ char smem[];
    const int tid    = threadIdx.x;
    const int lane   = tid & 31;
    const int wid    = tid >> 5;
    const int warp_m = wid & 1;          // 0..1 -> 64-row slab
    const int warp_n = wid >> 1;         // 0..3 -> 32-col slab
    const int m0 = blockIdx.y * 128;
    const int n0 = blockIdx.x * 128;

    const float* Xb = X + (size_t)m0 * 512;
    const float* Wb = W + (size_t)n0 * 512;

    // per-thread gmem load slots: 4 float4 for A, 4 for B per chunk
    const int lrow = tid >> 3;           // 0..31 base row step handled via idx
    (void)lrow;

    float acc[4][4][4];
#pragma unroll
    for (int i = 0; i < 4; ++i)
#pragma unroll
        for (int j = 0; j < 4; ++j)
#pragma unroll
            for (int q = 0; q < 4; ++q) acc[i][j][q] = 0.0f;

    float4 ar[4], br[4];

    auto load_regs = [&](int c) {
#pragma unroll
        for (int it = 0; it < 4; ++it) {
            int idx = it * 256 + tid;            // 0..1023 float4 slots
            int row = idx >> 3, c4 = idx & 7;    // 8 float4 per 32-float row
            ar[it] = *(const float4*)(Xb + (size_t)row * 512 + c * 32 + c4 * 4);
            br[it] = *(const float4*)(Wb + (size_t)row * 512 + c * 32 + c4 * 4);
        }
    };

    auto store_stage = [&](int s) {
        char* base = smem + s * STAGE_BYTES;
        __nv_bfloat16* Ah = (__nv_bfloat16*)(base);
        __nv_bfloat16* Al = (__nv_bfloat16*)(base + TILE_BYTES);
        __nv_bfloat16* Bh = (__nv_bfloat16*)(base + 2 * TILE_BYTES);
        __nv_bfloat16* Bl = (__nv_bfloat16*)(base + 3 * TILE_BYTES);
#pragma unroll
        for (int it = 0; it < 4; ++it) {
            int idx = it * 256 + tid;
            int row = idx >> 3, c4 = idx & 7;
            float4 v = ar[it];
            float hx = __bfloat162float(__float2bfloat16_rn(v.x));
            float hy = __bfloat162float(__float2bfloat16_rn(v.y));
            float hz = __bfloat162float(__float2bfloat16_rn(v.z));
            float hw = __bfloat162float(__float2bfloat16_rn(v.w));
            uint32_t* p = (uint32_t*)&Ah[row * LDT + c4 * 4];
            p[0] = pack_bf16(hx, hy);
            p[1] = pack_bf16(hz, hw);
            uint32_t* pl = (uint32_t*)&Al[row * LDT + c4 * 4];
            pl[0] = pack_bf16(v.x - hx, v.y - hy);
            pl[1] = pack_bf16(v.z - hz, v.w - hw);

            v = br[it];
            hx = __bfloat162float(__float2bfloat16_rn(v.x));
            hy = __bfloat162float(__float2bfloat16_rn(v.y));
            hz = __bfloat162float(__float2bfloat16_rn(v.z));
            hw = __bfloat162float(__float2bfloat16_rn(v.w));
            p = (uint32_t*)&Bh[row * LDT + c4 * 4];
            p[0] = pack_bf16(hx, hy);
            p[1] = pack_bf16(hz, hw);
            pl = (uint32_t*)&Bl[row * LDT + c4 * 4];
            pl[0] = pack_bf16(v.x - hx, v.y - hy);
            pl[1] = pack_bf16(v.z - hz, v.w - hw);
        }
    };

    load_regs(0);
    store_stage(0);
    __syncthreads();

    for (int c = 0; c < 16; ++c) {
        if (c + 1 < 16) load_regs(c + 1);

        const int s = c & 1;
        const char* base = smem + s * STAGE_BYTES;
        const __nv_bfloat16* Ah = (const __nv_bfloat16*)(base);
        const __nv_bfloat16* Al = (const __nv_bfloat16*)(base + TILE_BYTES);
        const __nv_bfloat16* Bh = (const __nv_bfloat16*)(base + 2 * TILE_BYTES);
        const __nv_bfloat16* Bl = (const __nv_bfloat16*)(base + 3 * TILE_BYTES);

#pragma unroll
        for (int kf = 0; kf < 2; ++kf) {
            const int kb = kf * 16 + (lane & 3) * 2;
            uint32_t bh[4][2], bl[4][2];
#pragma unroll
            for (int nf = 0; nf < 4; ++nf) {
                int n = warp_n * 32 + nf * 8 + (lane >> 2);
                bh[nf][0] = *(const uint32_t*)&Bh[n * LDT + kb];
                bh[nf][1] = *(const uint32_t*)&Bh[n * LDT + kb + 8];
                bl[nf][0] = *(const uint32_t*)&Bl[n * LDT + kb];
                bl[nf][1] = *(const uint32_t*)&Bl[n * LDT + kb + 8];
            }
#pragma unroll
            for (int mf = 0; mf < 4; ++mf) {
                int m = warp_m * 64 + mf * 16 + (lane >> 2);
                uint32_t ah[4], al[4];
                ah[0] = *(const uint32_t*)&Ah[m * LDT + kb];
                ah[1] = *(const uint32_t*)&Ah[(m + 8) * LDT + kb];
                ah[2] = *(const uint32_t*)&Ah[m * LDT + kb + 8];
                ah[3] = *(const uint32_t*)&Ah[(m + 8) * LDT + kb + 8];
                al[0] = *(const uint32_t*)&Al[m * LDT + kb];
                al[1] = *(const uint32_t*)&Al[(m + 8) * LDT + kb];
                al[2] = *(const uint32_t*)&Al[m * LDT + kb + 8];
                al[3] = *(const uint32_t*)&Al[(m + 8) * LDT + kb + 8];
#pragma unroll
                for (int nf = 0; nf < 4; ++nf) {
                    mma_bf16(acc[mf][nf], ah, bh[nf]);
                    mma_bf16(acc[mf][nf], ah, bl[nf]);
                    mma_bf16(acc[mf][nf], al, bh[nf]);
                }
            }
        }

        if (c + 1 < 16) store_stage((c + 1) & 1);
        __syncthreads();
    }

    // epilogue: c0,c1 -> (r, col..col+1); c2,c3 -> (r+8, col..col+1)
    const int rbase = m0 + warp_m * 64 + (lane >> 2);
    const int cbase = n0 + warp_n * 32 + (lane & 3) * 2;
#pragma unroll
    for (int mf = 0; mf < 4; ++mf) {
#pragma unroll
        for (int nf = 0; nf < 4; ++nf) {
            int col = cbase + nf * 8;
            float b0 = bias[col], b1 = bias[col + 1];
            float* p0 = out + (size_t)(rbase + mf * 16) * 512 + col;
            float* p1 = p0 + 8 * 512;
            float2 v0 = {acc[mf][nf][0] + b0, acc[mf][nf][1] + b1};
            float2 v1 = {acc[mf][nf][2] + b0, acc[mf][nf][3] + b1};
            *(float2*)p0 = v0;
            *(float2*)p1 = v1;
        }
    }
}

__global__ void __launch_bounds__(256, 1)
gemm_qkv_kernel(const float* __restrict__ xq, const float* __restrict__ xk,
                const float* __restrict__ xv,
                const float* __restrict__ Wq, const float* __restrict__ bq,
                const float* __restrict__ Wk, const float* __restrict__ bk,
                const float* __restrict__ Wv, const float* __restrict__ bv) {
    if (blockIdx.z == 0)      gemm_mma_body(xq, Wq, bq, g_q);
    else if (blockIdx.z == 1) gemm_mma_body(xk, Wk, bk, g_k);
    else                      gemm_mma_body(xv, Wv, bv, g_v);
}

__global__ void __launch_bounds__(256, 1)
gemm_o_kernel(const float* __restrict__ Wo, const float* __restrict__ bo,
              float* __restrict__ out) {
    gemm_mma_body(g_y, Wo, bo, out);
}

// ---------------- column max of pos_bias, 2-phase --------------------------
__global__ void colmax_part_kernel(const float* __restrict__ pb) {
    int c  = blockIdx.x * 256 + threadIdx.x;
    int r0 = blockIdx.y * 64;
    float m = -3.402823e38f;
#pragma unroll 4
    for (int r = 0; r < 64; ++r)
        m = fmaxf(m, pb[(size_t)(r0 + r) * T_LEN + c]);
    g_colmax_part[blockIdx.y * T_LEN + c] = m;
}

__global__ void colmax_comb_kernel() {
    int c = blockIdx.x * 256 + threadIdx.x;
    float m = -3.402823e38f;
#pragma unroll
    for (int i = 0; i < 32; ++i)
        m = fmaxf(m, g_colmax_part[i * T_LEN + c]);
    g_pbmax[c] = fmaxf(m, 0.0f);
}

// ---------------- max_logit[d] = max_t ( k[t,0,d] + relu(pbmax[t]) ) ----------
__global__ void ml_part_kernel() {
    int d  = blockIdx.x * 256 + threadIdx.x;
    int t0 = blockIdx.y * 32;
    float m = -3.402823e38f;
#pragma unroll 8
    for (int tt = 0; tt < 32; ++tt) {
        int t = t0 + tt;
        m = fmaxf(m, g_k[(size_t)t * BDIM + d] + g_pbmax[t]);
    }
    g_ml_part[blockIdx.y * DMODEL + d] = m;
}

__global__ void ml_comb_kernel() {
    int d = blockIdx.x * 256 + threadIdx.x;
    float m = -3.402823e38f;
#pragma unroll
    for (int i = 0; i < NCHUNK; ++i) m = fmaxf(m, g_ml_part[i * DMODEL + d]);
    g_ml[d] = m;
}

// ---------------- 3-phase parallel scan over t (64 chunks x 32) ---------------
__global__ void scan_partial_kernel() {
    int bd = blockIdx.x * 256 + threadIdx.x;
    int c  = blockIdx.y;
    int d  = bd & (DMODEL - 1);
    float ml = g_ml[d];
    float sn = 0.0f, sd = 0.0f;
    size_t base = (size_t)c * 32 * BDIM + bd;
#pragma unroll 8
    for (int i = 0; i < 32; ++i) {
        size_t off = base + (size_t)i * BDIM;
        float e  = __expf(g_k[off] - ml);
        float ev = e * g_v[off];
        g_ek[off]  = e;
        g_ekv[off] = ev;
        sn += ev;
        sd += e;
    }
    g_psn[c * BDIM + bd] = sn;
    g_psd[c * BDIM + bd] = sd;
}

__global__ void __launch_bounds__(1024) scan_prefix_kernel() {
    int bd = threadIdx.x;
    float sn = 0.0f, sd = 0.0f;
#pragma unroll 4
    for (int c = 0; c < NCHUNK; ++c) {
        float tn = g_psn[c * BDIM + bd];
        float td = g_psd[c * BDIM + bd];
        g_psn[c * BDIM + bd] = sn;
        g_psd[c * BDIM + bd] = sd;
        sn += tn;
        sd += td;
    }
}

__global__ void scan_final_kernel() {
    int bd = blockIdx.x * 256 + threadIdx.x;
    int c  = blockIdx.y;
    float sn = g_psn[c * BDIM + bd];
    float sd = g_psd[c * BDIM + bd];
    size_t base = (size_t)c * 32 * BDIM + bd;
#pragma unroll 8
    for (int i = 0; i < 32; ++i) {
        size_t off = base + (size_t)i * BDIM;
        sn += g_ekv[off];
        sd += g_ek[off];
        g_csn[off] = sn;
        g_csd[off] = sd;
    }
}

// ---------------- expw[t,j] = exp(pb[t, t-S+1+j]) ----------------------------
__global__ void expw_kernel(const float* __restrict__ pb) {
    int i = blockIdx.x * 256 + threadIdx.x;
    int t = i >> 5;
    int j = i & 31;
    int idx = t - SWIN + 1 + j;
    g_expw[i] = (idx >= 0) ? __expf(pb[(size_t)t * T_LEN + idx]) : 0.0f;
}

// ---------------- window + prefix combine -------------------------------------
__global__ void __launch_bounds__(256) aft_out_kernel() {
    __shared__ float wgt[4 * SWIN];
    int bd = blockIdx.x * 256 + threadIdx.x;
    int t0 = blockIdx.y * 4;

    if (threadIdx.x < 4 * SWIN) {
        int r = threadIdx.x >> 5;
        int j = threadIdx.x & 31;
        wgt[threadIdx.x] = g_expw[(t0 + r) * SWIN + j];
    }
    __syncthreads();

    float num[4] = {0.f, 0.f, 0.f, 0.f};
    float den[4] = {0.f, 0.f, 0.f, 0.f};

    int lo = t0 - SWIN + 1;
    if (lo < 0) lo = 0;

    for (int idx = lo; idx <= t0 + 3; ++idx) {
        size_t off = (size_t)idx * BDIM + bd;
        float ek  = g_ek[off];
        float ekv = g_ekv[off];
#pragma unroll
        for (int r = 0; r < 4; ++r) {
            int t = t0 + r;
            int j = idx - t + SWIN - 1;
            if (j >= 0 && j < SWIN) {
                float w = wgt[r * SWIN + j];
                num[r] += w * ekv;
                den[r] += w * ek;
            }
        }
    }

#pragma unroll
    for (int r = 0; r < 4; ++r) {
        int t = t0 + r;
        float n = num[r], dn = den[r];
        if (t >= SWIN) {
            size_t poff = (size_t)(t - SWIN) * BDIM + bd;
            n  += g_csn[poff];
            dn += g_csd[poff];
        }
        size_t off = (size_t)t * BDIM + bd;
        float q  = g_q[off];
        float sg = 1.0f / (1.0f + __expf(-q));
        g_y[off] = sg * n / dn;
    }
}

// ---------------- launch ------------------------------------------------------
extern "C" void kernel_launch(void* const* d_in, const int* in_sizes, int n_in,
                              void* d_out, int out_size) {
    const float* query = (const float*)d_in[0];
    const float* key   = (const float*)d_in[1];
    const float* value = (const float*)d_in[2];
    const float* Wq    = (const float*)d_in[3];
    const float* bq    = (const float*)d_in[4];
    const float* Wk    = (const float*)d_in[5];
    const float* bk    = (const float*)d_in[6];
    const float* Wv    = (const float*)d_in[7];
    const float* bv    = (const float*)d_in[8];
    const float* pb    = (const float*)d_in[9];
    const float* Wo    = (const float*)d_in[10];
    const float* bo    = (const float*)d_in[11];
    float* out = (float*)d_out;

    cudaFuncSetAttribute(gemm_qkv_kernel,
                         cudaFuncAttributeMaxDynamicSharedMemorySize, SMEM_MMA);
    cudaFuncSetAttribute(gemm_o_kernel,
                         cudaFuncAttributeMaxDynamicSharedMemorySize, SMEM_MMA);

    colmax_part_kernel<<<dim3(8, 32), 256>>>(pb);
    colmax_comb_kernel<<<8, 256>>>();

    gemm_qkv_kernel<<<dim3(4, 32, 3), 256, SMEM_MMA>>>(
        query, key, value, Wq, bq, Wk, bk, Wv, bv);

    ml_part_kernel<<<dim3(2, 64), 256>>>();
    ml_comb_kernel<<<2, 256>>>();

    scan_partial_kernel<<<dim3(4, 64), 256>>>();
    scan_prefix_kernel<<<1, 1024>>>();
    scan_final_kernel<<<dim3(4, 64), 256>>>();

    expw_kernel<<<(T_LEN * SWIN) / 256, 256>>>(pb);

    aft_out_kernel<<<dim3(4, 512), 256>>>();

    gemm_o_kernel<<<dim3(4, 32), 256, SMEM_MMA>>>(Wo, bo, out);
}

// round 8
// speedup vs baseline: 5.2114x; 1.0735x over previous
#include <cuda_runtime.h>
#include <cuda_bf16.h>
#include <cstdint>

#define T_LEN  2048
#define NBATCH 2
#define DMODEL 512
#define SWIN   32
#define MROWS  4096      // T_LEN * NBATCH
#define BDIM   1024      // NBATCH * DMODEL
#define NCHUNK 64        // T_LEN / 32

// ---------------- device scratch (allocation-free rule: __device__ globals) ----
__device__ float  g_q  [MROWS * DMODEL];
__device__ float  g_k  [MROWS * DMODEL];
__device__ float  g_v  [MROWS * DMODEL];
__device__ float  g_y  [MROWS * DMODEL];
__device__ float2 g_ekk[T_LEN * BDIM];          // (ek, ek*v) packed
__device__ float2 g_ps2[NCHUNK * BDIM];         // chunk partials -> exclusive prefix
__device__ float  g_colmax_part[32 * T_LEN];
__device__ float  g_pbmax[T_LEN];
__device__ float  g_ml_part[128 * DMODEL];
__device__ float  g_ml[DMODEL];
__device__ float2 g_expw2[T_LEN * SWIN];        // (w, w) duplicated weights

// ---------------- packed f32x2 helpers ----------------------------------------
__device__ __forceinline__ unsigned long long pack2(float lo, float hi) {
    unsigned long long r;
    asm("mov.b64 %0, {%1, %2};" : "=l"(r) : "f"(lo), "f"(hi));
    return r;
}
__device__ __forceinline__ void unpack2(unsigned long long v, float& lo, float& hi) {
    asm("mov.b64 {%0, %1}, %2;" : "=f"(lo), "=f"(hi) : "l"(v));
}
__device__ __forceinline__ unsigned long long ffma2(unsigned long long a,
                                                    unsigned long long b,
                                                    unsigned long long c) {
    unsigned long long d;
    asm("fma.rn.f32x2 %0, %1, %2, %3;" : "=l"(d) : "l"(a), "l"(b), "l"(c));
    return d;
}
__device__ __forceinline__ unsigned long long add2(unsigned long long a,
                                                   unsigned long long b) {
    unsigned long long d;
    asm("add.rn.f32x2 %0, %1, %2;" : "=l"(d) : "l"(a), "l"(b));
    return d;
}

// ================= bf16x3 split-precision warp-MMA GEMM ========================
#define LDT     40                       // bf16 elems per smem row (32 + 8 pad)
#define TILE_BYTES (128 * LDT * 2)       // 10240 B
#define STAGE_BYTES (4 * TILE_BYTES)     // Ah, Al, Bh, Bl
#define SMEM_MMA (2 * STAGE_BYTES)       // 81920 B

__device__ __forceinline__ uint32_t pack_bf16(float a, float b) {
    __nv_bfloat162 t = __floats2bfloat162_rn(a, b);
    return *(uint32_t*)&t;
}
__device__ __forceinline__ uint32_t smem_u32(const void* p) {
    uint32_t a;
    asm("{ .reg .u64 t; cvta.to.shared.u64 t, %1; cvt.u32.u64 %0, t; }"
        : "=r"(a) : "l"(p));
    return a;
}
__device__ __forceinline__ void ldsm4(uint32_t* r, uint32_t a) {
    asm volatile("ldmatrix.sync.aligned.m8n8.x4.shared.b16 {%0,%1,%2,%3}, [%4];"
                 : "=r"(r[0]), "=r"(r[1]), "=r"(r[2]), "=r"(r[3]) : "r"(a));
}
__device__ __forceinline__ void mma_bf16(float* c, const uint32_t* a, const uint32_t* b) {
    asm volatile(
        "mma.sync.aligned.m16n8k16.row.col.f32.bf16.bf16.f32 "
        "{%0,%1,%2,%3}, {%4,%5,%6,%7}, {%8,%9}, {%0,%1,%2,%3};"
        : "+f"(c[0]), "+f"(c[1]), "+f"(c[2]), "+f"(c[3])
        : "r"(a[0]), "r"(a[1]), "r"(a[2]), "r"(a[3]), "r"(b[0]), "r"(b[1]));
}

__device__ __forceinline__ void gemm_mma_body(const float* __restrict__ X,
                                              const float* __restrict__ W,
                                              const float* __restrict__ bias,
                                              float* __restrict__ out) {
    extern __shared__ char smem[];
    const int tid    = threadIdx.x;
    const int lane   = tid & 31;
    const int wid    = tid >> 5;
    const int warp_m = wid & 1;
    const int warp_n = wid >> 1;
    const int m0 = blockIdx.y * 128;
    const int n0 = blockIdx.x * 128;

    const float* Xb = X + (size_t)m0 * 512;
    const float* Wb = W + (size_t)n0 * 512;

    const uint32_t sbase = smem_u32(smem);
    // ldmatrix lane offsets (bytes)
    const uint32_t a_off = ((warp_m * 64 + (lane & 15)) * LDT + ((lane >> 4) * 8)) * 2;
    const uint32_t b_off = ((warp_n * 32 + (lane & 7) + ((lane >> 4) & 1) * 8) * LDT
                            + (((lane >> 3) & 1) * 8)) * 2;

    float acc[4][4][4];
#pragma unroll
    for (int i = 0; i < 4; ++i)
#pragma unroll
        for (int j = 0; j < 4; ++j)
#pragma unroll
            for (int q = 0; q < 4; ++q) acc[i][j][q] = 0.0f;

    float4 ar[4], br[4];

    auto load_regs = [&](int c) {
#pragma unroll
        for (int it = 0; it < 4; ++it) {
            int idx = it * 256 + tid;
            int row = idx >> 3, c4 = idx & 7;
            ar[it] = *(const float4*)(Xb + (size_t)row * 512 + c * 32 + c4 * 4);
            br[it] = *(const float4*)(Wb + (size_t)row * 512 + c * 32 + c4 * 4);
        }
    };

    auto store_stage = [&](int s) {
        char* base = smem + s * STAGE_BYTES;
        __nv_bfloat16* Ah = (__nv_bfloat16*)(base);
        __nv_bfloat16* Al = (__nv_bfloat16*)(base + TILE_BYTES);
        __nv_bfloat16* Bh = (__nv_bfloat16*)(base + 2 * TILE_BYTES);
        __nv_bfloat16* Bl = (__nv_bfloat16*)(base + 3 * TILE_BYTES);
#pragma unroll
        for (int it = 0; it < 4; ++it) {
            int idx = it * 256 + tid;
            int row = idx >> 3, c4 = idx & 7;
            float4 v = ar[it];
            float hx = __bfloat162float(__float2bfloat16_rn(v.x));
            float hy = __bfloat162float(__float2bfloat16_rn(v.y));
            float hz = __bfloat162float(__float2bfloat16_rn(v.z));
            float hw = __bfloat162float(__float2bfloat16_rn(v.w));
            uint32_t* p = (uint32_t*)&Ah[row * LDT + c4 * 4];
            p[0] = pack_bf16(hx, hy);
            p[1] = pack_bf16(hz, hw);
            uint32_t* pl = (uint32_t*)&Al[row * LDT + c4 * 4];
            pl[0] = pack_bf16(v.x - hx, v.y - hy);
            pl[1] = pack_bf16(v.z - hz, v.w - hw);

            v = br[it];
            hx = __bfloat162float(__float2bfloat16_rn(v.x));
            hy = __bfloat162float(__float2bfloat16_rn(v.y));
            hz = __bfloat162float(__float2bfloat16_rn(v.z));
            hw = __bfloat162float(__float2bfloat16_rn(v.w));
            p = (uint32_t*)&Bh[row * LDT + c4 * 4];
            p[0] = pack_bf16(hx, hy);
            p[1] = pack_bf16(hz, hw);
            pl = (uint32_t*)&Bl[row * LDT + c4 * 4];
            pl[0] = pack_bf16(v.x - hx, v.y - hy);
            pl[1] = pack_bf16(v.z - hz, v.w - hw);
        }
    };

    load_regs(0);
    store_stage(0);
    __syncthreads();

    for (int c = 0; c < 16; ++c) {
        if (c + 1 < 16) load_regs(c + 1);

        const uint32_t sa = sbase + (c & 1) * STAGE_BYTES;

#pragma unroll
        for (int kf = 0; kf < 2; ++kf) {
            const uint32_t kb = kf * 32;    // 16 bf16 = 32 bytes
            uint32_t bh4[2][4], bl4[2][4];
#pragma unroll
            for (int p = 0; p < 2; ++p) {
                uint32_t ba = sa + 2 * TILE_BYTES + b_off + p * (16 * LDT * 2) + kb;
                ldsm4(bh4[p], ba);
                ldsm4(bl4[p], ba + TILE_BYTES);
            }
#pragma unroll
            for (int mf = 0; mf < 4; ++mf) {
                uint32_t aa = sa + a_off + mf * (16 * LDT * 2) + kb;
                uint32_t ah[4], al[4];
                ldsm4(ah, aa);
                ldsm4(al, aa + TILE_BYTES);
#pragma unroll
                for (int nf = 0; nf < 4; ++nf) {
                    const uint32_t* bh = &bh4[nf >> 1][(nf & 1) * 2];
                    const uint32_t* bl = &bl4[nf >> 1][(nf & 1) * 2];
                    mma_bf16(acc[mf][nf], ah, bh);
                    mma_bf16(acc[mf][nf], ah, bl);
                    mma_bf16(acc[mf][nf], al, bh);
                }
            }
        }

        if (c + 1 < 16) store_stage((c + 1) & 1);
        __syncthreads();
    }

    const int rbase = m0 + warp_m * 64 + (lane >> 2);
    const int cbase = n0 + warp_n * 32 + (lane & 3) * 2;
#pragma unroll
    for (int mf = 0; mf < 4; ++mf) {
#pragma unroll
        for (int nf = 0; nf < 4; ++nf) {
            int col = cbase + nf * 8;
            float b0 = bias[col], b1 = bias[col + 1];
            float* p0 = out + (size_t)(rbase + mf * 16) * 512 + col;
            float* p1 = p0 + 8 * 512;
            float2 v0 = {acc[mf][nf][0] + b0, acc[mf][nf][1] + b1};
            float2 v1 = {acc[mf][nf][2] + b0, acc[mf][nf][3] + b1};
            *(float2*)p0 = v0;
            *(float2*)p1 = v1;
        }
    }
}

__global__ void __launch_bounds__(256, 1)
gemm_qkv_kernel(const float* __restrict__ xq, const float* __restrict__ xk,
                const float* __restrict__ xv,
                const float* __restrict__ Wq, const float* __restrict__ bq,
                const float* __restrict__ Wk, const float* __restrict__ bk,
                const float* __restrict__ Wv, const float* __restrict__ bv) {
    if (blockIdx.z == 0)      gemm_mma_body(xq, Wq, bq, g_q);
    else if (blockIdx.z == 1) gemm_mma_body(xk, Wk, bk, g_k);
    else                      gemm_mma_body(xv, Wv, bv, g_v);
}

__global__ void __launch_bounds__(256, 1)
gemm_o_kernel(const float* __restrict__ Wo, const float* __restrict__ bo,
              float* __restrict__ out) {
    gemm_mma_body(g_y, Wo, bo, out);
}

// ---------------- column max of pos_bias, phase 1 ------------------------------
__global__ void colmax_part_kernel(const float* __restrict__ pb) {
    int c  = blockIdx.x * 256 + threadIdx.x;
    int r0 = blockIdx.y * 64;
    float m = -3.402823e38f;
#pragma unroll 4
    for (int r = 0; r < 64; ++r)
        m = fmaxf(m, pb[(size_t)(r0 + r) * T_LEN + c]);
    g_colmax_part[blockIdx.y * T_LEN + c] = m;
}

// ---------------- phase 2 merged with expw2 (both depend only on pb/colmax) ----
__global__ void colmax_expw_kernel(const float* __restrict__ pb) {
    if (blockIdx.x < 8) {
        int c = blockIdx.x * 256 + threadIdx.x;
        float m = -3.402823e38f;
#pragma unroll
        for (int i = 0; i < 32; ++i)
            m = fmaxf(m, g_colmax_part[i * T_LEN + c]);
        g_pbmax[c] = fmaxf(m, 0.0f);                 // relu folded
    } else {
        int i = (blockIdx.x - 8) * 256 + threadIdx.x;  // 0..65535
        int t = i >> 5;
        int j = i & 31;
        int idx = t - SWIN + 1 + j;
        float w = (idx >= 0) ? __expf(pb[(size_t)t * T_LEN + idx]) : 0.0f;
        g_expw2[i] = make_float2(w, w);
    }
}

// ---------------- max_logit[d] = max_t ( k[t,0,d] + relu(pbmax[t]) ) ----------
__global__ void ml_part_kernel() {
    int d  = blockIdx.x * 256 + threadIdx.x;     // 0..511
    int t0 = blockIdx.y * 16;
    float m0 = -3.402823e38f, m1 = m0, m2 = m0, m3 = m0;
#pragma unroll
    for (int tt = 0; tt < 16; tt += 4) {
        int t = t0 + tt;
        m0 = fmaxf(m0, g_k[(size_t)(t + 0) * BDIM + d] + g_pbmax[t + 0]);
        m1 = fmaxf(m1, g_k[(size_t)(t + 1) * BDIM + d] + g_pbmax[t + 1]);
        m2 = fmaxf(m2, g_k[(size_t)(t + 2) * BDIM + d] + g_pbmax[t + 2]);
        m3 = fmaxf(m3, g_k[(size_t)(t + 3) * BDIM + d] + g_pbmax[t + 3]);
    }
    g_ml_part[blockIdx.y * DMODEL + d] = fmaxf(fmaxf(m0, m1), fmaxf(m2, m3));
}

__global__ void ml_comb_kernel() {
    int d = blockIdx.x * 256 + threadIdx.x;
    float m = -3.402823e38f;
#pragma unroll 8
    for (int i = 0; i < 128; ++i) m = fmaxf(m, g_ml_part[i * DMODEL + d]);
    g_ml[d] = m;
}

// ---------------- scan phase A: ek/ekv (packed) + per-chunk sums ---------------
__global__ void scan_partial_kernel() {
    int bd = blockIdx.x * 256 + threadIdx.x;
    int c  = blockIdx.y;
    float ml = g_ml[bd & (DMODEL - 1)];
    float sd = 0.0f, sn = 0.0f;
    size_t base = (size_t)c * 32 * BDIM + bd;
#pragma unroll 8
    for (int i = 0; i < 32; ++i) {
        size_t off = base + (size_t)i * BDIM;
        float e  = __expf(g_k[off] - ml);
        float ev = e * g_v[off];
        g_ekk[off] = make_float2(e, ev);
        sd += e;
        sn += ev;
    }
    g_ps2[c * BDIM + bd] = make_float2(sd, sn);
}

// ---------------- scan phase B: exclusive prefix over 64 chunks (MLP 16) -------
__global__ void scan_prefix_kernel() {
    int bd = blockIdx.x * 256 + threadIdx.x;     // 0..1023
    float sx = 0.0f, sy = 0.0f;
    for (int cb = 0; cb < NCHUNK; cb += 16) {
        float2 v[16];
#pragma unroll
        for (int j = 0; j < 16; ++j) v[j] = g_ps2[(cb + j) * BDIM + bd];
#pragma unroll
        for (int j = 0; j < 16; ++j) {
            float2 t = v[j];
            g_ps2[(cb + j) * BDIM + bd] = make_float2(sx, sy);
            sx += t.x;
            sy += t.y;
        }
    }
}

// ---------------- fused window + cumsum + combine: y = sig(q)*num/den ----------
// Thread = (bd, 32-t chunk). cs snapshots folded into acc; csn/csd never hit gmem.
__global__ void __launch_bounds__(256) aft_fused_kernel() {
    __shared__ float2 w2s[32 * SWIN];
    const int tid = threadIdx.x;
    const int bd  = blockIdx.x * 256 + tid;
    const int c   = blockIdx.y;
    const int t0  = c * 32;

#pragma unroll
    for (int it = 0; it < 4; ++it) {
        int idx = it * 256 + tid;
        w2s[idx] = g_expw2[t0 * SWIN + idx];
    }
    __syncthreads();

    unsigned long long acc[32];
#pragma unroll
    for (int r = 0; r < 32; ++r) acc[r] = 0ULL;

    if (c > 0) {
        float2 ps = g_ps2[(c - 1) * BDIM + bd];
        unsigned long long cs2 = pack2(ps.x, ps.y);
        // rows of chunk c-1: cumsum snapshots + leading window contributions
#pragma unroll
        for (int i = 0; i < 32; ++i) {
            float2 e = g_ekk[(size_t)(t0 - 32 + i) * BDIM + bd];
            unsigned long long e2 = pack2(e.x, e.y);
            cs2 = add2(cs2, e2);
            acc[i] = add2(acc[i], cs2);          // cs at t = t0+i (prefix idx t-32)
#pragma unroll
            for (int r = 0; r < 31; ++r) {
                if (r < i)                        // compile-time after unroll
                    acc[r] = ffma2(*(const unsigned long long*)&w2s[r * 32 + (i - r - 1)],
                                   e2, acc[r]);
            }
        }
    }
    // rows of chunk c: trailing window contributions
#pragma unroll
    for (int i = 0; i < 32; ++i) {
        float2 e = g_ekk[(size_t)(t0 + i) * BDIM + bd];
        unsigned long long e2 = pack2(e.x, e.y);
#pragma unroll
        for (int r = 0; r < 32; ++r) {
            if (r >= i)
                acc[r] = ffma2(*(const unsigned long long*)&w2s[r * 32 + (i - r + 31)],
                               e2, acc[r]);
        }
    }

#pragma unroll
    for (int r = 0; r < 32; ++r) {
        float den, num;
        unpack2(acc[r], den, num);
        size_t off = (size_t)(t0 + r) * BDIM + bd;
        float q  = g_q[off];
        float sg = 1.0f / (1.0f + __expf(-q));
        g_y[off] = sg * num / den;
    }
}

// ---------------- launch ------------------------------------------------------
extern "C" void kernel_launch(void* const* d_in, const int* in_sizes, int n_in,
                              void* d_out, int out_size) {
    const float* query = (const float*)d_in[0];
    const float* key   = (const float*)d_in[1];
    const float* value = (const float*)d_in[2];
    const float* Wq    = (const float*)d_in[3];
    const float* bq    = (const float*)d_in[4];
    const float* Wk    = (const float*)d_in[5];
    const float* bk    = (const float*)d_in[6];
    const float* Wv    = (const float*)d_in[7];
    const float* bv    = (const float*)d_in[8];
    const float* pb    = (const float*)d_in[9];
    const float* Wo    = (const float*)d_in[10];
    const float* bo    = (const float*)d_in[11];
    float* out = (float*)d_out;

    cudaFuncSetAttribute(gemm_qkv_kernel,
                         cudaFuncAttributeMaxDynamicSharedMemorySize, SMEM_MMA);
    cudaFuncSetAttribute(gemm_o_kernel,
                         cudaFuncAttributeMaxDynamicSharedMemorySize, SMEM_MMA);

    colmax_part_kernel<<<dim3(8, 32), 256>>>(pb);
    colmax_expw_kernel<<<8 + 256, 256>>>(pb);

    gemm_qkv_kernel<<<dim3(4, 32, 3), 256, SMEM_MMA>>>(
        query, key, value, Wq, bq, Wk, bk, Wv, bv);

    ml_part_kernel<<<dim3(2, 128), 256>>>();
    ml_comb_kernel<<<2, 256>>>();

    scan_partial_kernel<<<dim3(4, 64), 256>>>();
    scan_prefix_kernel<<<4, 256>>>();

    aft_fused_kernel<<<dim3(4, 64), 256>>>();

    gemm_o_kernel<<<dim3(4, 32), 256, SMEM_MMA>>>(Wo, bo, out);
}